// round 7
// baseline (speedup 1.0000x reference)
#include <cuda_runtime.h>

// Elementwise CGP model — MLP=8 retry with relaxed register budget.
//   n7 = __sinf(x0*x1 + c0) * (x2*x3) + __sinf(x2)
//   n8 = __cosf(n7)*c1 + x0
//
// R4 failed at MLP=8 because __launch_bounds__(256,8) capped regs at 32,
// so 8 float4 loads could not stay in flight. This retries MLP=8 with
// __launch_bounds__(256,4): regs free to ~48+, occupancy-limited to ~4-5
// CTA/SM, latency covered by per-thread MLP instead of warp count.
//
// Block owns 2048 consecutive rows; thread t handles rows base + 256*k + t:
//   - 8 front-batched LDG.128 via __ldcs (zero-reuse stream)
//   - 8 STG.64 via __stcs

__device__ __forceinline__ float2 cgp_row(float4 x, float c0, float c1) {
    float n4 = __fmaf_rn(x.x, x.y, c0);
    float n5 = __sinf(n4);
    float n6 = x.z * x.w;
    float n7 = __fmaf_rn(n5, n6, __sinf(x.z));
    float n8 = __fmaf_rn(__cosf(n7), c1, x.x);
    return make_float2(n7, n8);
}

__global__ void __launch_bounds__(256, 4)
cgp_kernel(const float4* __restrict__ X,
           const float* __restrict__ ephs,
           float2* __restrict__ out) {
    const int base = blockIdx.x * 2048 + threadIdx.x;

    const float c0 = __ldg(&ephs[0]);
    const float c1 = __ldg(&ephs[1]);

    // Front-batched coalesced streaming loads, MLP=8.
    float4 x0 = __ldcs(&X[base + 0 * 256]);
    float4 x1 = __ldcs(&X[base + 1 * 256]);
    float4 x2 = __ldcs(&X[base + 2 * 256]);
    float4 x3 = __ldcs(&X[base + 3 * 256]);
    float4 x4 = __ldcs(&X[base + 4 * 256]);
    float4 x5 = __ldcs(&X[base + 5 * 256]);
    float4 x6 = __ldcs(&X[base + 6 * 256]);
    float4 x7 = __ldcs(&X[base + 7 * 256]);

    __stcs(&out[base + 0 * 256], cgp_row(x0, c0, c1));
    __stcs(&out[base + 1 * 256], cgp_row(x1, c0, c1));
    __stcs(&out[base + 2 * 256], cgp_row(x2, c0, c1));
    __stcs(&out[base + 3 * 256], cgp_row(x3, c0, c1));
    __stcs(&out[base + 4 * 256], cgp_row(x4, c0, c1));
    __stcs(&out[base + 5 * 256], cgp_row(x5, c0, c1));
    __stcs(&out[base + 6 * 256], cgp_row(x6, c0, c1));
    __stcs(&out[base + 7 * 256], cgp_row(x7, c0, c1));
}

extern "C" void kernel_launch(void* const* d_in, const int* in_sizes, int n_in,
                              void* d_out, int out_size) {
    const float4* X   = (const float4*)d_in[0];   // (B, 4) float32, one float4/row
    const float*  eph = (const float*)d_in[1];    // (2,)   float32
    float2*       out = (float2*)d_out;           // (B, 2) float32, one float2/row

    int B = in_sizes[0] / 4;       // rows = 8388608
    int blocks = B / 2048;         // 2048 rows per block (B divisible)

    cgp_kernel<<<blocks, 256>>>(X, eph, out);
}

// round 8
// speedup vs baseline: 1.0790x; 1.0790x over previous
#include <cuda_runtime.h>

// Elementwise CGP model — evict-first loads + evict-NORMAL stores.
//   n7 = __sinf(x0*x1 + c0) * (x2*x3) + __sinf(x2)
//   n8 = __cosf(n7)*c1 + x0
//
// Placement theory: output (67MB) fits in L2 (126MB). X (134MB) is a
// zero-reuse stream. Load X with __ldcs (evict-first: never claims L2
// residency) and store with DEFAULT policy (evict-normal: output lines
// stay L2-resident), so the DRAM write stream is absorbed by L2 and
// DRAM traffic approaches read-only (~134MB).
//
// Block owns 1024 consecutive rows; thread t handles rows base + 256*k + t:
//   - 4 front-batched LDG.128 via __ldcs (lane stride 16B, full lines)
//   - 4 STG.64 default policy (lane stride 8B, full lines)

__device__ __forceinline__ float2 cgp_row(float4 x, float c0, float c1) {
    float n4 = __fmaf_rn(x.x, x.y, c0);
    float n5 = __sinf(n4);
    float n6 = x.z * x.w;
    float n7 = __fmaf_rn(n5, n6, __sinf(x.z));
    float n8 = __fmaf_rn(__cosf(n7), c1, x.x);
    return make_float2(n7, n8);
}

__global__ void __launch_bounds__(256, 8)
cgp_kernel(const float4* __restrict__ X,
           const float* __restrict__ ephs,
           float2* __restrict__ out) {
    const int base = blockIdx.x * 1024 + threadIdx.x;

    const float c0 = __ldg(&ephs[0]);
    const float c1 = __ldg(&ephs[1]);

    // Front-batched coalesced streaming loads, MLP=4.
    float4 a = __ldcs(&X[base + 0]);
    float4 b = __ldcs(&X[base + 256]);
    float4 c = __ldcs(&X[base + 512]);
    float4 d = __ldcs(&X[base + 768]);

    // Default-policy stores: let the output claim L2 residency.
    out[base + 0]   = cgp_row(a, c0, c1);
    out[base + 256] = cgp_row(b, c0, c1);
    out[base + 512] = cgp_row(c, c0, c1);
    out[base + 768] = cgp_row(d, c0, c1);
}

extern "C" void kernel_launch(void* const* d_in, const int* in_sizes, int n_in,
                              void* d_out, int out_size) {
    const float4* X   = (const float4*)d_in[0];   // (B, 4) float32, one float4/row
    const float*  eph = (const float*)d_in[1];    // (2,)   float32
    float2*       out = (float2*)d_out;           // (B, 2) float32, one float2/row

    int B = in_sizes[0] / 4;       // rows = 8388608
    int blocks = B / 1024;         // 1024 rows per block (B divisible)

    cgp_kernel<<<blocks, 256>>>(X, eph, out);
}